// round 16
// baseline (speedup 1.0000x reference)
#include <cuda_runtime.h>
#include <math.h>

#define B_    32
#define H_    6
#define W_    2400
#define C_    64
#define OV_   4
#define G_    3
#define NVQ_  6
#define K_    1024
#define D_    8
#define FIX_  384
#define GD_   512
#define T_    600
#define NPG   (B_*T_)              // 19200
#define NPTS  (G_*NPG)             // 57600
#define ZQ_SIZE  (B_*H_*W_*C_)     // 29491200
#define IDX_SIZE (B_*NVQ_*G_*T_)   // 345600
#define RVQ_BLOCKS 1800
#define KD_GRID   148
#define KD_TILES  1600             // 32 b x 50 tiles of 12 t

__device__ float g_en8s[G_*NVQ_*K_*D_];  // 8-split rvq codebooks
__device__ float g_pd2 [G_*6144];        // pd masked/permuted: per g, A[768u]+B[768u] 16B units
__device__ float g_zd [G_*NPG*D_];
__device__ float g_zqd[G_*NPG*D_];
__device__ float g_partial[RVQ_BLOCKS];

__device__ __forceinline__ unsigned smem_u32(const void* p) {
    return (unsigned)__cvta_generic_to_shared(p);
}
__device__ __forceinline__ void cp16(float* dst, const float* src) {
    asm volatile("cp.async.ca.shared.global [%0], [%1], 16;"
                 :: "r"(smem_u32(dst)), "l"(src));
}

// ---------------------------------------------------------------------------
// K0: dummy to steer ncu capture window (4th launch = k_down).
// ---------------------------------------------------------------------------
__global__ void k_dummy() {
    if (threadIdx.x == 0) g_partial[0] = 0.f;
}

// ---------------------------------------------------------------------------
// K1: normalize codebook rows, 8-split layout.
// ---------------------------------------------------------------------------
__global__ void k_norm(const float* __restrict__ cb) {
    int r = blockIdx.x * blockDim.x + threadIdx.x;
    if (r >= G_*NVQ_*K_) return;
    const float* src = cb + (size_t)r * D_;
    float v[8]; float ss = 0.f;
#pragma unroll
    for (int d = 0; d < 8; d++) { v[d] = src[d]; ss = fmaf(v[d], v[d], ss); }
    float inv = 1.0f / fmaxf(sqrtf(ss), 1e-12f);
    int gi = r >> 10, k = r & 1023;
    int s = k >> 7, jl = (k & 127) >> 1, half = k & 1;
    float* d2 = g_en8s + (size_t)gi*(K_*D_) + jl*128 + s*4 + half;
#pragma unroll
    for (int d = 0; d < 8; d++)
        d2[(d >> 1)*32 + (d & 1)*2] = v[d] * inv;
}

// ---------------------------------------------------------------------------
// K1b: repack proj_down for the z-address-order dot product.
// For group g, z covers o-blocks {g, g+1} (768 floats at z2 offset g*384).
// pd value masked to dims belonging to group g, permuted to z2 order
// (addr a: o=a/384, h=(a%384)/64, c=a%64 -> dim = o*384 + c*6 + h).
// Packed f32x2 pairs (halves 2dp, 2dp+1); A = dims q0,q1; B = dims q2,q3.
// unit index = m*8 + dp*2 + jh  (a4 = 2m + jh, a = 4*a4 + q)
// ---------------------------------------------------------------------------
__global__ void k_prep(const float* __restrict__ pd) {
    int r = blockIdx.x * blockDim.x + threadIdx.x;
    if (r >= G_*4*192) return;                 // 2304
    int g   = r / 768, rem = r % 768;
    int dp  = rem / 192, a4 = rem % 192;
    int m   = a4 >> 1, jh = a4 & 1;
    float vals[8];
#pragma unroll
    for (int q = 0; q < 4; q++) {
        int A  = g*384 + 4*a4 + q;
        int o  = A / 384;
        int rr = A - o*384;
        int h  = rr >> 6, c = rr & 63;
        int dim = o*FIX_ + c*6 + h;
        float v0 = 0.f, v1 = 0.f;
        if ((dim >> 9) == g) {
            int col = dim - g*GD_;
            v0 = pd[(size_t)(g*8 + 2*dp)*GD_ + col];
            v1 = pd[(size_t)(g*8 + 2*dp + 1)*GD_ + col];
        }
        vals[q*2] = v0; vals[q*2+1] = v1;
    }
    float* gA = g_pd2 + g*6144 + (m*8 + dp*2 + jh)*4;
    float* gB = gA + 3072;
    gA[0]=vals[0]; gA[1]=vals[1]; gA[2]=vals[2]; gA[3]=vals[3];
    gB[0]=vals[4]; gB[1]=vals[5]; gB[2]=vals[6]; gB[3]=vals[7];
}

// ---------------------------------------------------------------------------
// K2 v6b: persistent double-buffered pipeline (R15 + pB unit-stride FIX).
// ---------------------------------------------------------------------------
#define ZROW 1544
#define ZBUF (12*ZROW)                       // 18528 floats
#define KD_SMEM ((2*ZBUF + G_*6144) * 4)     // 221952 bytes

__device__ __forceinline__ void kd_stage(float* zbuf, const float* __restrict__ ze,
                                         int b, int w0, int tid) {
#pragma unroll
    for (int k = 0; k < 16; k++) {
        int chunk = tid + k*288;             // 0..4607
        int row = chunk >> 4;                // (tl*4+o)*6 + h
        int c4  = chunk & 15;
        int h   = row % 6;
        int wl  = row / 6;                   // 0..47
        float* dst = zbuf + (wl >> 2)*ZROW + (wl & 3)*FIX_ + h*64 + c4*4;
        const float* src = ze + ((size_t)(b*H_ + h)*W_ + w0 + wl)*C_ + c4*4;
        cp16(dst, src);
    }
}

__global__ void __launch_bounds__(288) k_down(const float* __restrict__ ze,
                                              const float* __restrict__ unused) {
    extern __shared__ float sm[];
    float* zb0 = sm;
    float* zb1 = sm + ZBUF;
    float* sP  = sm + 2*ZBUF;
    int tid = threadIdx.x;
    int bid = blockIdx.x;

    // prologue: pd + first tile
#pragma unroll
    for (int k = 0; k < 16; k++) {
        int idx = (tid + k*288)*4;
        cp16(sP + idx, g_pd2 + idx);
    }
    {
        int b = bid / 50, tile = bid % 50;
        kd_stage(zb0, ze, b, tile*48, tid);
    }
    asm volatile("cp.async.commit_group;" ::: "memory");

    int w = tid >> 5, l = tid & 31;
    int g = w / 3, tw = w % 3;
    int idx = tw*32 + l;                 // 0..95
    int tl  = idx >> 3;
    int dp  = (idx >> 1) & 3;
    int jh  = idx & 1;
    const ulonglong2* pA = (const ulonglong2*)(sP + g*6144);
    const ulonglong2* pB = pA + 768;     // B section: +3072 floats = +768 16B-units
    int punit = dp*2 + jh;

    int it = 0;
    for (int tt = bid; tt < KD_TILES; tt += KD_GRID, it++) {
        int nxt = tt + KD_GRID;
        if (nxt < KD_TILES) {
            int b = nxt / 50, tile = nxt % 50;
            kd_stage(((it + 1) & 1) ? zb1 : zb0, ze, b, tile*48, tid);
            asm volatile("cp.async.commit_group;" ::: "memory");
            asm volatile("cp.async.wait_group 1;" ::: "memory");
        } else {
            asm volatile("cp.async.wait_group 0;" ::: "memory");
        }
        __syncthreads();

        float* zbuf = (it & 1) ? zb1 : zb0;
        const float* zr = zbuf + tl*ZROW + g*FIX_;

        unsigned long long acc;
        asm("mov.b64 %0, {%1, %1};" : "=l"(acc) : "f"(0.0f));
#pragma unroll 4
        for (int m = 0; m < 96; m++) {
            float4 z4 = *(const float4*)(zr + (2*m + jh)*4);
            unsigned long long zx, zy, zz, zw;
            asm("mov.b64 %0, {%1, %1};" : "=l"(zx) : "f"(z4.x));
            asm("mov.b64 %0, {%1, %1};" : "=l"(zy) : "f"(z4.y));
            asm("mov.b64 %0, {%1, %1};" : "=l"(zz) : "f"(z4.z));
            asm("mov.b64 %0, {%1, %1};" : "=l"(zw) : "f"(z4.w));
            ulonglong2 uA = pA[m*8 + punit];
            ulonglong2 uB = pB[m*8 + punit];
            asm("fma.rn.f32x2 %0, %1, %2, %0;" : "+l"(acc) : "l"(zx), "l"(uA.x));
            asm("fma.rn.f32x2 %0, %1, %2, %0;" : "+l"(acc) : "l"(zy), "l"(uA.y));
            asm("fma.rn.f32x2 %0, %1, %2, %0;" : "+l"(acc) : "l"(zz), "l"(uB.x));
            asm("fma.rn.f32x2 %0, %1, %2, %0;" : "+l"(acc) : "l"(zw), "l"(uB.y));
        }
        unsigned long long other = __shfl_xor_sync(0xffffffffu, acc, 1);
        asm("add.rn.f32x2 %0, %0, %1;" : "+l"(acc) : "l"(other));
        if (jh == 0) {
            int b = tt / 50, tile = tt % 50;
            float a0, a1;
            asm("mov.b64 {%0, %1}, %2;" : "=f"(a0), "=f"(a1) : "l"(acc));
            *(float2*)(g_zd + ((size_t)g*NPG + b*T_ + tile*12 + tl)*D_ + 2*dp)
                = make_float2(a0, a1);
        }
        __syncthreads();
    }
}

// ---------------------------------------------------------------------------
// K3: residual VQ (R10 version: 64 thr = 8 slots x 8 splits, 4 pts/thread).
// ---------------------------------------------------------------------------
__device__ __forceinline__ int combine8(float best, int bk) {
    unsigned bits = __float_as_uint(best);
    unsigned su = bits ^ (unsigned)(((int)bits >> 31) | 0x80000000);
    unsigned long long key = ((unsigned long long)su << 10) | (unsigned)(1023 - bk);
    unsigned long long o = __shfl_xor_sync(0xffffffffu, key, 1);
    key = (o > key) ? o : key;
    o = __shfl_xor_sync(0xffffffffu, key, 2);
    key = (o > key) ? o : key;
    o = __shfl_xor_sync(0xffffffffu, key, 4);
    key = (o > key) ? o : key;
    return 1023 - (int)(key & 1023u);
}

__global__ void __launch_bounds__(64, 7) k_rvq(float* __restrict__ out_codes) {
    __shared__ float sE[K_*D_];
    __shared__ float sWarp[2];
    int bid  = blockIdx.x;
    int g    = bid / (RVQ_BLOCKS/G_);
    int lb   = bid % (RVQ_BLOCKS/G_);
    int tid  = threadIdx.x;
    int slot = tid >> 3;
    int s    = tid & 7;
    int pl0  = lb*32 + slot*4;
    int p0   = g*NPG + pl0;

    unsigned long long r2[4][8];
    {
        const float4* zd4 = (const float4*)g_zd;
#pragma unroll
        for (int m = 0; m < 4; m++) {
            float4 lo = zd4[(size_t)(p0+m)*2], hi = zd4[(size_t)(p0+m)*2+1];
            float rv[8] = { lo.x, lo.y, lo.z, lo.w, hi.x, hi.y, hi.z, hi.w };
#pragma unroll
            for (int d = 0; d < 8; d++)
                asm("mov.b64 %0, {%1, %1};" : "=l"(r2[m][d]) : "f"(rv[d]));
        }
    }
    int ofs[4];
#pragma unroll
    for (int m = 0; m < 4; m++) {
        int pl = pl0 + m;
        int b = pl / T_, t = pl - b*T_;
        ofs[m] = (b*NVQ_*G_ + g)*T_ + t;
    }

    float sse = 0.f;

    for (int i = 0; i < NVQ_; i++) {
        __syncthreads();
        {
            const float4* src = (const float4*)(g_en8s + (size_t)(g*NVQ_ + i)*(K_*D_));
            float4* dst = (float4*)sE;
#pragma unroll
            for (int j = 0; j < 32; j++) dst[tid + j*64] = src[tid + j*64];
        }
        __syncthreads();

        const ulonglong2* e2 = (const ulonglong2*)sE;
        float best0 = -3.0e38f, best1 = -3.0e38f, best2v = -3.0e38f, best3 = -3.0e38f;
        int bk0 = 0, bk1 = 0, bk2 = 0, bk3 = 0;
#pragma unroll 2
        for (int j = 0; j < 64; j++) {
            int base = j*32 + s;
            ulonglong2 c0 = e2[base];
            ulonglong2 c1 = e2[base + 8];
            ulonglong2 c2 = e2[base + 16];
            ulonglong2 c3 = e2[base + 24];
#define SIM(mm, ACC) \
            asm("mul.rn.f32x2 %0, %1, %2;"     : "=l"(ACC) : "l"(r2[mm][0]), "l"(c0.x)); \
            asm("fma.rn.f32x2 %0, %1, %2, %0;" : "+l"(ACC) : "l"(r2[mm][1]), "l"(c0.y)); \
            asm("fma.rn.f32x2 %0, %1, %2, %0;" : "+l"(ACC) : "l"(r2[mm][2]), "l"(c1.x)); \
            asm("fma.rn.f32x2 %0, %1, %2, %0;" : "+l"(ACC) : "l"(r2[mm][3]), "l"(c1.y)); \
            asm("fma.rn.f32x2 %0, %1, %2, %0;" : "+l"(ACC) : "l"(r2[mm][4]), "l"(c2.x)); \
            asm("fma.rn.f32x2 %0, %1, %2, %0;" : "+l"(ACC) : "l"(r2[mm][5]), "l"(c2.y)); \
            asm("fma.rn.f32x2 %0, %1, %2, %0;" : "+l"(ACC) : "l"(r2[mm][6]), "l"(c3.x)); \
            asm("fma.rn.f32x2 %0, %1, %2, %0;" : "+l"(ACC) : "l"(r2[mm][7]), "l"(c3.y));
            unsigned long long a0, a1, a2, a3;
            SIM(0, a0) SIM(1, a1) SIM(2, a2) SIM(3, a3)
#undef SIM
            float lo, hi, m;
            int cand;
            asm("mov.b64 {%0, %1}, %2;" : "=f"(lo), "=f"(hi) : "l"(a0));
            m = fmaxf(lo, hi); cand = 2*j + ((hi > lo) ? 1 : 0);
            if (m > best0) { best0 = m; bk0 = cand; }
            asm("mov.b64 {%0, %1}, %2;" : "=f"(lo), "=f"(hi) : "l"(a1));
            m = fmaxf(lo, hi); cand = 2*j + ((hi > lo) ? 1 : 0);
            if (m > best1) { best1 = m; bk1 = cand; }
            asm("mov.b64 {%0, %1}, %2;" : "=f"(lo), "=f"(hi) : "l"(a2));
            m = fmaxf(lo, hi); cand = 2*j + ((hi > lo) ? 1 : 0);
            if (m > best2v) { best2v = m; bk2 = cand; }
            asm("mov.b64 {%0, %1}, %2;" : "=f"(lo), "=f"(hi) : "l"(a3));
            m = fmaxf(lo, hi); cand = 2*j + ((hi > lo) ? 1 : 0);
            if (m > best3) { best3 = m; bk3 = cand; }
        }
        int kk0 = combine8(best0, s*128 + bk0);
        int kk1 = combine8(best1, s*128 + bk1);
        int kk2 = combine8(best2v, s*128 + bk2);
        int kk3 = combine8(best3, s*128 + bk3);

#define UPD(mm, KVAL) { \
            int k = (KVAL); \
            int base = ((k & 127) >> 1)*128 + ((k >> 7) << 2) + (k & 1); \
            float ss = 0.f; \
            _Pragma("unroll") \
            for (int d = 0; d < 8; d++) { \
                float ev = sE[base + (d >> 1)*32 + (d & 1)*2]; \
                float rlo; \
                asm("mov.b64 {%0, _}, %1;" : "=f"(rlo) : "l"(r2[mm][d])); \
                float rn = rlo - ev; \
                asm("mov.b64 %0, {%1, %1};" : "=l"(r2[mm][d]) : "f"(rn)); \
                ss = fmaf(rn, rn, ss); \
            } \
            sse += ss; }
        UPD(0, kk0) UPD(1, kk1) UPD(2, kk2) UPD(3, kk3)
#undef UPD

        if (s == 0) {
            float* oc = out_codes + (size_t)i*(G_*T_);
            oc[ofs[0]] = (float)kk0;
            oc[ofs[1]] = (float)kk1;
            oc[ofs[2]] = (float)kk2;
            oc[ofs[3]] = (float)kk3;
        }
    }

    if (s == 0) {
        const float4* zd4 = (const float4*)g_zd;
        float4* zq4 = (float4*)g_zqd;
#pragma unroll
        for (int m = 0; m < 4; m++) {
            float4 lo = zd4[(size_t)(p0+m)*2], hi = zd4[(size_t)(p0+m)*2+1];
            float zv[8] = { lo.x, lo.y, lo.z, lo.w, hi.x, hi.y, hi.z, hi.w };
            float qv[8];
#pragma unroll
            for (int d = 0; d < 8; d++) {
                float rlo;
                asm("mov.b64 {%0, _}, %1;" : "=f"(rlo) : "l"(r2[m][d]));
                qv[d] = zv[d] - rlo;
            }
            zq4[(size_t)(p0+m)*2]   = make_float4(qv[0], qv[1], qv[2], qv[3]);
            zq4[(size_t)(p0+m)*2+1] = make_float4(qv[4], qv[5], qv[6], qv[7]);
        }
    }

    float c = (s == 0) ? sse : 0.f;
#pragma unroll
    for (int off = 16; off > 0; off >>= 1)
        c += __shfl_down_sync(0xffffffffu, c, off);
    int lane = tid & 31, wid = tid >> 5;
    if (lane == 0) sWarp[wid] = c;
    __syncthreads();
    if (tid == 0) g_partial[bid] = sWarp[0] + sWarp[1];
}

// ---------------------------------------------------------------------------
// K4: proj_up fused with post_process (R5 version, 33us).
// ---------------------------------------------------------------------------
#define TT 25
__global__ void __launch_bounds__(256) k_up(const float* __restrict__ pu, float* __restrict__ out) {
    __shared__ float sZ[G_*TT*D_];
    int bid  = blockIdx.x;
    int b    = bid / (T_/TT);
    int tile = bid % (T_/TT);
    int t0   = tile * TT;
    int tid  = threadIdx.x;

    for (int idx = tid; idx < G_*TT*D_; idx += 256) {
        int g  = idx / (TT*D_);
        int rr = idx % (TT*D_);
        sZ[idx] = g_zqd[((size_t)g*NPG + b*T_ + t0)*D_ + rr];
    }
    __syncthreads();

    int wid = tid >> 5, lane = tid & 31;
    for (int task = wid; task < 48; task += 8) {
        int o   = task / 12;
        int rem = task % 12;
        int h   = rem >> 1;
        int ch  = rem & 1;
        int c   = ch*32 + lane;
        int pp  = o*FIX_ + c*6 + h;
        int g   = pp >> 9;
        const float4* pu4 = (const float4*)pu + (size_t)pp*2;
        float4 pl = __ldg(pu4), ph = __ldg(pu4 + 1);
        float* op = out + ((size_t)(b*H_ + h)*W_ + 4*t0 + o)*C_ + c;
        const float4* zb = (const float4*)(sZ + g*(TT*D_));
#pragma unroll 5
        for (int tl = 0; tl < TT; tl++) {
            float4 zl = zb[tl*2], zh = zb[tl*2 + 1];
            float s0 = zl.x*pl.x, s1 = zl.y*pl.y;
            s0 = fmaf(zl.z, pl.z, s0); s1 = fmaf(zl.w, pl.w, s1);
            s0 = fmaf(zh.x, ph.x, s0); s1 = fmaf(zh.y, ph.y, s1);
            s0 = fmaf(zh.z, ph.z, s0); s1 = fmaf(zh.w, ph.w, s1);
            op[(size_t)tl*4*C_] = s0 + s1;
        }
    }
}

// ---------------------------------------------------------------------------
// K5: final deterministic loss reduction.
// ---------------------------------------------------------------------------
__global__ void k_final(float* __restrict__ d_out) {
    __shared__ float s[512];
    int tid = threadIdx.x;
    float v = 0.f;
    for (int idx = tid; idx < RVQ_BLOCKS; idx += 512) v += g_partial[idx];
    s[tid] = v; __syncthreads();
    for (int off = 256; off > 0; off >>= 1) {
        if (tid < off) s[tid] += s[tid + off];
        __syncthreads();
    }
    if (tid == 0) {
        float loss = s[0] / (float)(G_ * B_ * T_ * D_);
        d_out[ZQ_SIZE + IDX_SIZE]     = loss;
        d_out[ZQ_SIZE + IDX_SIZE + 1] = loss;
    }
}

// ---------------------------------------------------------------------------
extern "C" void kernel_launch(void* const* d_in, const int* in_sizes, int n_in,
                              void* d_out, int out_size) {
    const float* z_e = (const float*)d_in[0];
    const float* pd  = (const float*)d_in[1];
    const float* pu  = (const float*)d_in[2];
    const float* cb  = (const float*)d_in[3];
    float* out = (float*)d_out;

    cudaFuncSetAttribute(k_down, cudaFuncAttributeMaxDynamicSharedMemorySize, KD_SMEM);

    k_dummy<<<1, 32>>>();                               // launch steering
    k_norm<<<(G_*NVQ_*K_ + 255)/256, 256>>>(cb);
    k_prep<<<9, 256>>>(pd);
    k_down<<<KD_GRID, 288, KD_SMEM>>>(z_e, pd);         // 4th launch -> ncu
    k_rvq<<<RVQ_BLOCKS, 64>>>(out + ZQ_SIZE);
    k_up<<<B_*(T_/TT), 256>>>(pu, out);
    k_final<<<1, 512>>>(out);
}

// round 17
// speedup vs baseline: 1.0673x; 1.0673x over previous
#include <cuda_runtime.h>
#include <math.h>

#define B_    32
#define H_    6
#define W_    2400
#define C_    64
#define OV_   4
#define G_    3
#define NVQ_  6
#define K_    1024
#define D_    8
#define FIX_  384
#define GD_   512
#define T_    600
#define NPG   (B_*T_)              // 19200
#define NPTS  (G_*NPG)             // 57600
#define ZQ_SIZE  (B_*H_*W_*C_)     // 29491200
#define IDX_SIZE (B_*NVQ_*G_*T_)   // 345600
#define RVQ_BLOCKS 1800
#define KD_GRID   148
#define KD_TILES  1600             // 32 b x 50 tiles of 12 t

__device__ float g_en8s[G_*NVQ_*K_*D_];  // 8-split rvq codebooks
__device__ float g_pd2 [G_*6144];        // pd masked/permuted
__device__ float g_zd [G_*NPG*D_];
__device__ float g_zqd[G_*NPG*D_];
__device__ float g_partial[RVQ_BLOCKS];

__device__ __forceinline__ unsigned smem_u32(const void* p) {
    return (unsigned)__cvta_generic_to_shared(p);
}
__device__ __forceinline__ void cp16(float* dst, const float* src) {
    asm volatile("cp.async.cg.shared.global [%0], [%1], 16;"
                 :: "r"(smem_u32(dst)), "l"(src));
}

// ---------------------------------------------------------------------------
// K1: normalize codebook rows, 8-split layout.
// ---------------------------------------------------------------------------
__global__ void k_norm(const float* __restrict__ cb) {
    int r = blockIdx.x * blockDim.x + threadIdx.x;
    if (r >= G_*NVQ_*K_) return;
    const float* src = cb + (size_t)r * D_;
    float v[8]; float ss = 0.f;
#pragma unroll
    for (int d = 0; d < 8; d++) { v[d] = src[d]; ss = fmaf(v[d], v[d], ss); }
    float inv = 1.0f / fmaxf(sqrtf(ss), 1e-12f);
    int gi = r >> 10, k = r & 1023;
    int s = k >> 7, jl = (k & 127) >> 1, half = k & 1;
    float* d2 = g_en8s + (size_t)gi*(K_*D_) + jl*128 + s*4 + half;
#pragma unroll
    for (int d = 0; d < 8; d++)
        d2[(d >> 1)*32 + (d & 1)*2] = v[d] * inv;
}

// ---------------------------------------------------------------------------
// K1b: repack proj_down (zero-masked, z-address-order, f32x2 pairs).
// ---------------------------------------------------------------------------
__global__ void k_prep(const float* __restrict__ pd) {
    int r = blockIdx.x * blockDim.x + threadIdx.x;
    if (r >= G_*4*192) return;                 // 2304
    int g   = r / 768, rem = r % 768;
    int dp  = rem / 192, a4 = rem % 192;
    int m   = a4 >> 1, jh = a4 & 1;
    float vals[8];
#pragma unroll
    for (int q = 0; q < 4; q++) {
        int A  = g*384 + 4*a4 + q;
        int o  = A / 384;
        int rr = A - o*384;
        int h  = rr >> 6, c = rr & 63;
        int dim = o*FIX_ + c*6 + h;
        float v0 = 0.f, v1 = 0.f;
        if ((dim >> 9) == g) {
            int col = dim - g*GD_;
            v0 = pd[(size_t)(g*8 + 2*dp)*GD_ + col];
            v1 = pd[(size_t)(g*8 + 2*dp + 1)*GD_ + col];
        }
        vals[q*2] = v0; vals[q*2+1] = v1;
    }
    float* gA = g_pd2 + g*6144 + (m*8 + dp*2 + jh)*4;
    float* gB = gA + 3072;
    gA[0]=vals[0]; gA[1]=vals[1]; gA[2]=vals[2]; gA[3]=vals[3];
    gB[0]=vals[4]; gB[1]=vals[5]; gB[2]=vals[6]; gB[3]=vals[7];
}

// ---------------------------------------------------------------------------
// K2 v6c: persistent double-buffered pipeline, cp.async.cg (L1 bypass).
// ---------------------------------------------------------------------------
#define ZROW 1544
#define ZBUF (12*ZROW)
#define KD_SMEM ((2*ZBUF + G_*6144) * 4)     // 221952 bytes

__device__ __forceinline__ void kd_stage(float* zbuf, const float* __restrict__ ze,
                                         int b, int w0, int tid) {
#pragma unroll
    for (int k = 0; k < 16; k++) {
        int chunk = tid + k*288;
        int row = chunk >> 4;
        int c4  = chunk & 15;
        int h   = row % 6;
        int wl  = row / 6;
        float* dst = zbuf + (wl >> 2)*ZROW + (wl & 3)*FIX_ + h*64 + c4*4;
        const float* src = ze + ((size_t)(b*H_ + h)*W_ + w0 + wl)*C_ + c4*4;
        cp16(dst, src);
    }
}

__global__ void __launch_bounds__(288) k_down(const float* __restrict__ ze,
                                              const float* __restrict__ unused) {
    extern __shared__ float sm[];
    float* zb0 = sm;
    float* zb1 = sm + ZBUF;
    float* sP  = sm + 2*ZBUF;
    int tid = threadIdx.x;
    int bid = blockIdx.x;

#pragma unroll
    for (int k = 0; k < 16; k++) {
        int idx = (tid + k*288)*4;
        cp16(sP + idx, g_pd2 + idx);
    }
    {
        int b = bid / 50, tile = bid % 50;
        kd_stage(zb0, ze, b, tile*48, tid);
    }
    asm volatile("cp.async.commit_group;" ::: "memory");

    int w = tid >> 5, l = tid & 31;
    int g = w / 3, tw = w % 3;
    int idx = tw*32 + l;
    int tl  = idx >> 3;
    int dp  = (idx >> 1) & 3;
    int jh  = idx & 1;
    const ulonglong2* pA = (const ulonglong2*)(sP + g*6144);
    const ulonglong2* pB = pA + 768;
    int punit = dp*2 + jh;

    int it = 0;
    for (int tt = bid; tt < KD_TILES; tt += KD_GRID, it++) {
        int nxt = tt + KD_GRID;
        if (nxt < KD_TILES) {
            int b = nxt / 50, tile = nxt % 50;
            kd_stage(((it + 1) & 1) ? zb1 : zb0, ze, b, tile*48, tid);
            asm volatile("cp.async.commit_group;" ::: "memory");
            asm volatile("cp.async.wait_group 1;" ::: "memory");
        } else {
            asm volatile("cp.async.wait_group 0;" ::: "memory");
        }
        __syncthreads();

        float* zbuf = (it & 1) ? zb1 : zb0;
        const float* zr = zbuf + tl*ZROW + g*FIX_;

        unsigned long long acc;
        asm("mov.b64 %0, {%1, %1};" : "=l"(acc) : "f"(0.0f));
#pragma unroll 4
        for (int m = 0; m < 96; m++) {
            float4 z4 = *(const float4*)(zr + (2*m + jh)*4);
            unsigned long long zx, zy, zz, zw;
            asm("mov.b64 %0, {%1, %1};" : "=l"(zx) : "f"(z4.x));
            asm("mov.b64 %0, {%1, %1};" : "=l"(zy) : "f"(z4.y));
            asm("mov.b64 %0, {%1, %1};" : "=l"(zz) : "f"(z4.z));
            asm("mov.b64 %0, {%1, %1};" : "=l"(zw) : "f"(z4.w));
            ulonglong2 uA = pA[m*8 + punit];
            ulonglong2 uB = pB[m*8 + punit];
            asm("fma.rn.f32x2 %0, %1, %2, %0;" : "+l"(acc) : "l"(zx), "l"(uA.x));
            asm("fma.rn.f32x2 %0, %1, %2, %0;" : "+l"(acc) : "l"(zy), "l"(uA.y));
            asm("fma.rn.f32x2 %0, %1, %2, %0;" : "+l"(acc) : "l"(zz), "l"(uB.x));
            asm("fma.rn.f32x2 %0, %1, %2, %0;" : "+l"(acc) : "l"(zw), "l"(uB.y));
        }
        unsigned long long other = __shfl_xor_sync(0xffffffffu, acc, 1);
        asm("add.rn.f32x2 %0, %0, %1;" : "+l"(acc) : "l"(other));
        if (jh == 0) {
            int b = tt / 50, tile = tt % 50;
            float a0, a1;
            asm("mov.b64 {%0, %1}, %2;" : "=f"(a0), "=f"(a1) : "l"(acc));
            *(float2*)(g_zd + ((size_t)g*NPG + b*T_ + tile*12 + tl)*D_ + 2*dp)
                = make_float2(a0, a1);
        }
        __syncthreads();
    }
}

// ---------------------------------------------------------------------------
// K3: residual VQ with software-pipelined codebook loads (prefetch j+1 hides
// the 29-cyc LDS latency in-warp).
// ---------------------------------------------------------------------------
__device__ __forceinline__ int combine8(float best, int bk) {
    unsigned bits = __float_as_uint(best);
    unsigned su = bits ^ (unsigned)(((int)bits >> 31) | 0x80000000);
    unsigned long long key = ((unsigned long long)su << 10) | (unsigned)(1023 - bk);
    unsigned long long o = __shfl_xor_sync(0xffffffffu, key, 1);
    key = (o > key) ? o : key;
    o = __shfl_xor_sync(0xffffffffu, key, 2);
    key = (o > key) ? o : key;
    o = __shfl_xor_sync(0xffffffffu, key, 4);
    key = (o > key) ? o : key;
    return 1023 - (int)(key & 1023u);
}

__global__ void __launch_bounds__(64, 6) k_rvq(float* __restrict__ out_codes) {
    __shared__ float sE[K_*D_];
    __shared__ float sWarp[2];
    int bid  = blockIdx.x;
    int g    = bid / (RVQ_BLOCKS/G_);
    int lb   = bid % (RVQ_BLOCKS/G_);
    int tid  = threadIdx.x;
    int slot = tid >> 3;
    int s    = tid & 7;
    int pl0  = lb*32 + slot*4;
    int p0   = g*NPG + pl0;

    unsigned long long r2[4][8];
    {
        const float4* zd4 = (const float4*)g_zd;
#pragma unroll
        for (int m = 0; m < 4; m++) {
            float4 lo = zd4[(size_t)(p0+m)*2], hi = zd4[(size_t)(p0+m)*2+1];
            float rv[8] = { lo.x, lo.y, lo.z, lo.w, hi.x, hi.y, hi.z, hi.w };
#pragma unroll
            for (int d = 0; d < 8; d++)
                asm("mov.b64 %0, {%1, %1};" : "=l"(r2[m][d]) : "f"(rv[d]));
        }
    }
    int ofs[4];
#pragma unroll
    for (int m = 0; m < 4; m++) {
        int pl = pl0 + m;
        int b = pl / T_, t = pl - b*T_;
        ofs[m] = (b*NVQ_*G_ + g)*T_ + t;
    }

    float sse = 0.f;

    for (int i = 0; i < NVQ_; i++) {
        __syncthreads();
        {
            const float4* src = (const float4*)(g_en8s + (size_t)(g*NVQ_ + i)*(K_*D_));
            float4* dst = (float4*)sE;
#pragma unroll
            for (int j = 0; j < 32; j++) dst[tid + j*64] = src[tid + j*64];
        }
        __syncthreads();

        const ulonglong2* e2 = (const ulonglong2*)sE;
        float best0 = -3.0e38f, best1 = -3.0e38f, best2v = -3.0e38f, best3 = -3.0e38f;
        int bk0 = 0, bk1 = 0, bk2 = 0, bk3 = 0;

        // prologue: load j=0
        ulonglong2 c0 = e2[s], c1 = e2[s + 8], c2 = e2[s + 16], c3 = e2[s + 24];
#pragma unroll 2
        for (int j = 0; j < 64; j++) {
            // prefetch j+1 (dead on last iteration)
            ulonglong2 n0, n1, n2, n3;
            if (j < 63) {
                int nb = (j + 1)*32 + s;
                n0 = e2[nb]; n1 = e2[nb + 8]; n2 = e2[nb + 16]; n3 = e2[nb + 24];
            } else {
                n0 = c0; n1 = c1; n2 = c2; n3 = c3;
            }
#define SIM(mm, ACC) \
            asm("mul.rn.f32x2 %0, %1, %2;"     : "=l"(ACC) : "l"(r2[mm][0]), "l"(c0.x)); \
            asm("fma.rn.f32x2 %0, %1, %2, %0;" : "+l"(ACC) : "l"(r2[mm][1]), "l"(c0.y)); \
            asm("fma.rn.f32x2 %0, %1, %2, %0;" : "+l"(ACC) : "l"(r2[mm][2]), "l"(c1.x)); \
            asm("fma.rn.f32x2 %0, %1, %2, %0;" : "+l"(ACC) : "l"(r2[mm][3]), "l"(c1.y)); \
            asm("fma.rn.f32x2 %0, %1, %2, %0;" : "+l"(ACC) : "l"(r2[mm][4]), "l"(c2.x)); \
            asm("fma.rn.f32x2 %0, %1, %2, %0;" : "+l"(ACC) : "l"(r2[mm][5]), "l"(c2.y)); \
            asm("fma.rn.f32x2 %0, %1, %2, %0;" : "+l"(ACC) : "l"(r2[mm][6]), "l"(c3.x)); \
            asm("fma.rn.f32x2 %0, %1, %2, %0;" : "+l"(ACC) : "l"(r2[mm][7]), "l"(c3.y));
            unsigned long long a0, a1, a2, a3;
            SIM(0, a0) SIM(1, a1) SIM(2, a2) SIM(3, a3)
#undef SIM
            float lo, hi, m;
            int cand;
            asm("mov.b64 {%0, %1}, %2;" : "=f"(lo), "=f"(hi) : "l"(a0));
            m = fmaxf(lo, hi); cand = 2*j + ((hi > lo) ? 1 : 0);
            if (m > best0) { best0 = m; bk0 = cand; }
            asm("mov.b64 {%0, %1}, %2;" : "=f"(lo), "=f"(hi) : "l"(a1));
            m = fmaxf(lo, hi); cand = 2*j + ((hi > lo) ? 1 : 0);
            if (m > best1) { best1 = m; bk1 = cand; }
            asm("mov.b64 {%0, %1}, %2;" : "=f"(lo), "=f"(hi) : "l"(a2));
            m = fmaxf(lo, hi); cand = 2*j + ((hi > lo) ? 1 : 0);
            if (m > best2v) { best2v = m; bk2 = cand; }
            asm("mov.b64 {%0, %1}, %2;" : "=f"(lo), "=f"(hi) : "l"(a3));
            m = fmaxf(lo, hi); cand = 2*j + ((hi > lo) ? 1 : 0);
            if (m > best3) { best3 = m; bk3 = cand; }
            c0 = n0; c1 = n1; c2 = n2; c3 = n3;
        }
        int kk0 = combine8(best0, s*128 + bk0);
        int kk1 = combine8(best1, s*128 + bk1);
        int kk2 = combine8(best2v, s*128 + bk2);
        int kk3 = combine8(best3, s*128 + bk3);

#define UPD(mm, KVAL) { \
            int k = (KVAL); \
            int base = ((k & 127) >> 1)*128 + ((k >> 7) << 2) + (k & 1); \
            float ss = 0.f; \
            _Pragma("unroll") \
            for (int d = 0; d < 8; d++) { \
                float ev = sE[base + (d >> 1)*32 + (d & 1)*2]; \
                float rlo; \
                asm("mov.b64 {%0, _}, %1;" : "=f"(rlo) : "l"(r2[mm][d])); \
                float rn = rlo - ev; \
                asm("mov.b64 %0, {%1, %1};" : "=l"(r2[mm][d]) : "f"(rn)); \
                ss = fmaf(rn, rn, ss); \
            } \
            sse += ss; }
        UPD(0, kk0) UPD(1, kk1) UPD(2, kk2) UPD(3, kk3)
#undef UPD

        if (s == 0) {
            float* oc = out_codes + (size_t)i*(G_*T_);
            oc[ofs[0]] = (float)kk0;
            oc[ofs[1]] = (float)kk1;
            oc[ofs[2]] = (float)kk2;
            oc[ofs[3]] = (float)kk3;
        }
    }

    if (s == 0) {
        const float4* zd4 = (const float4*)g_zd;
        float4* zq4 = (float4*)g_zqd;
#pragma unroll
        for (int m = 0; m < 4; m++) {
            float4 lo = zd4[(size_t)(p0+m)*2], hi = zd4[(size_t)(p0+m)*2+1];
            float zv[8] = { lo.x, lo.y, lo.z, lo.w, hi.x, hi.y, hi.z, hi.w };
            float qv[8];
#pragma unroll
            for (int d = 0; d < 8; d++) {
                float rlo;
                asm("mov.b64 {%0, _}, %1;" : "=f"(rlo) : "l"(r2[m][d]));
                qv[d] = zv[d] - rlo;
            }
            zq4[(size_t)(p0+m)*2]   = make_float4(qv[0], qv[1], qv[2], qv[3]);
            zq4[(size_t)(p0+m)*2+1] = make_float4(qv[4], qv[5], qv[6], qv[7]);
        }
    }

    float c = (s == 0) ? sse : 0.f;
#pragma unroll
    for (int off = 16; off > 0; off >>= 1)
        c += __shfl_down_sync(0xffffffffu, c, off);
    int lane = tid & 31, wid = tid >> 5;
    if (lane == 0) sWarp[wid] = c;
    __syncthreads();
    if (tid == 0) g_partial[bid] = sWarp[0] + sWarp[1];
}

// ---------------------------------------------------------------------------
// K4: proj_up fused with post_process (R5 version).
// ---------------------------------------------------------------------------
#define TT 25
__global__ void __launch_bounds__(256) k_up(const float* __restrict__ pu, float* __restrict__ out) {
    __shared__ float sZ[G_*TT*D_];
    int bid  = blockIdx.x;
    int b    = bid / (T_/TT);
    int tile = bid % (T_/TT);
    int t0   = tile * TT;
    int tid  = threadIdx.x;

    for (int idx = tid; idx < G_*TT*D_; idx += 256) {
        int g  = idx / (TT*D_);
        int rr = idx % (TT*D_);
        sZ[idx] = g_zqd[((size_t)g*NPG + b*T_ + t0)*D_ + rr];
    }
    __syncthreads();

    int wid = tid >> 5, lane = tid & 31;
    for (int task = wid; task < 48; task += 8) {
        int o   = task / 12;
        int rem = task % 12;
        int h   = rem >> 1;
        int ch  = rem & 1;
        int c   = ch*32 + lane;
        int pp  = o*FIX_ + c*6 + h;
        int g   = pp >> 9;
        const float4* pu4 = (const float4*)pu + (size_t)pp*2;
        float4 pl = __ldg(pu4), ph = __ldg(pu4 + 1);
        float* op = out + ((size_t)(b*H_ + h)*W_ + 4*t0 + o)*C_ + c;
        const float4* zb = (const float4*)(sZ + g*(TT*D_));
#pragma unroll 5
        for (int tl = 0; tl < TT; tl++) {
            float4 zl = zb[tl*2], zh = zb[tl*2 + 1];
            float s0 = zl.x*pl.x, s1 = zl.y*pl.y;
            s0 = fmaf(zl.z, pl.z, s0); s1 = fmaf(zl.w, pl.w, s1);
            s0 = fmaf(zh.x, ph.x, s0); s1 = fmaf(zh.y, ph.y, s1);
            s0 = fmaf(zh.z, ph.z, s0); s1 = fmaf(zh.w, ph.w, s1);
            op[(size_t)tl*4*C_] = s0 + s1;
        }
    }
}

// ---------------------------------------------------------------------------
// K5: final deterministic loss reduction.
// ---------------------------------------------------------------------------
__global__ void k_final(float* __restrict__ d_out) {
    __shared__ float s[512];
    int tid = threadIdx.x;
    float v = 0.f;
    for (int idx = tid; idx < RVQ_BLOCKS; idx += 512) v += g_partial[idx];
    s[tid] = v; __syncthreads();
    for (int off = 256; off > 0; off >>= 1) {
        if (tid < off) s[tid] += s[tid + off];
        __syncthreads();
    }
    if (tid == 0) {
        float loss = s[0] / (float)(G_ * B_ * T_ * D_);
        d_out[ZQ_SIZE + IDX_SIZE]     = loss;
        d_out[ZQ_SIZE + IDX_SIZE + 1] = loss;
    }
}

// ---------------------------------------------------------------------------
extern "C" void kernel_launch(void* const* d_in, const int* in_sizes, int n_in,
                              void* d_out, int out_size) {
    const float* z_e = (const float*)d_in[0];
    const float* pd  = (const float*)d_in[1];
    const float* pu  = (const float*)d_in[2];
    const float* cb  = (const float*)d_in[3];
    float* out = (float*)d_out;

    cudaFuncSetAttribute(k_down, cudaFuncAttributeMaxDynamicSharedMemorySize, KD_SMEM);

    k_norm<<<(G_*NVQ_*K_ + 255)/256, 256>>>(cb);
    k_prep<<<9, 256>>>(pd);
    k_down<<<KD_GRID, 288, KD_SMEM>>>(z_e, pd);
    k_rvq<<<RVQ_BLOCKS, 64>>>(out + ZQ_SIZE);           // 4th launch -> ncu
    k_up<<<B_*(T_/TT), 256>>>(pu, out);
    k_final<<<1, 512>>>(out);
}